// round 8
// baseline (speedup 1.0000x reference)
#include <cuda_runtime.h>
#include <cuda_fp16.h>

typedef unsigned int u32;
typedef unsigned short u16;

#define NFEAT 256
#define NPB   128          // nodes per CTA (m16 per warp)
#define NTHR  256

// ---- smem layout (bytes) ----
#define W_STRIDE 528                        // 64 rows x (512B + 16B pad): ldmatrix conflict-free
#define OFF_WH   0
#define OFF_X    33792                      // X ring: 8 stages x (8 warps x 16 rows x 64B)
#define XSTAGE   8192
#define NSTAGE   8
#define OFF_FC   (OFF_X + NSTAGE * XSTAGE)  // 99328
#define FCQ   0
#define FW2   512
#define FB1   544
#define FBZ   576
#define FBH   608
#define FB2   640
#define SMEM_BYTES (OFF_FC + 642 * 4)       // 101896 -> 2 CTAs/SM

// W folded: [n=64][k=256] row-major fp16
__device__ __align__(16) u16 g_Wh[64 * 256];
// fc1 packed for B-fragments: fc1q[jp][i] = {lo: fc1[2jp][i], hi: fc1[2jp+1][i]} fp16
__device__ __align__(16) u32 g_fc1q[16 * 32];

// ---------------------------------------------------------------------------
// Prep: fold wc[j][k] = (wz[0]+wz[1]) | (wh[0]+wh[1]) (x-rows only; h0=0 kills
// the H half of the concat and the r-gate). Also pack fc1 into b-frag layout.
// ---------------------------------------------------------------------------
__global__ void prep_kernel(const float* __restrict__ wz, const float* __restrict__ wh,
                            const float* __restrict__ fc1w) {
    int idx = blockIdx.x * 256 + threadIdx.x;
    if (idx < 64 * 256) {
        int j = idx >> 8, k = idx & 255;
        const int D1 = 288 * 32;
        float wc = (j < 32) ? (wz[k * 32 + j] + wz[D1 + k * 32 + j])
                            : (wh[k * 32 + (j - 32)] + wh[D1 + k * 32 + (j - 32)]);
        __half h = __float2half_rn(wc);
        g_Wh[j * 256 + k] = *reinterpret_cast<u16*>(&h);
    }
    if (idx < 512) {
        int jp = idx >> 5, i = idx & 31;
        __half lo = __float2half_rn(fc1w[(2 * jp) * 32 + i]);
        __half hi = __float2half_rn(fc1w[(2 * jp + 1) * 32 + i]);
        g_fc1q[idx] = ((u32)*reinterpret_cast<u16*>(&hi) << 16) | *reinterpret_cast<u16*>(&lo);
    }
}

// ---------------------------------------------------------------------------
// helpers
// ---------------------------------------------------------------------------
__device__ __forceinline__ u32 s2u(const void* p) {
    u32 a;
    asm("{ .reg .u64 t; cvta.to.shared.u64 t, %1; cvt.u32.u64 %0, t; }" : "=r"(a) : "l"(p));
    return a;
}
__device__ __forceinline__ void ldsm4(u32 a, u32& r0, u32& r1, u32& r2, u32& r3) {
    asm volatile("ldmatrix.sync.aligned.m8n8.x4.shared.b16 {%0,%1,%2,%3}, [%4];"
                 : "=r"(r0), "=r"(r1), "=r"(r2), "=r"(r3) : "r"(a));
}
__device__ __forceinline__ void mma16816(float* c, const u32* a, u32 b0, u32 b1) {
    asm volatile("mma.sync.aligned.m16n8k16.row.col.f32.f16.f16.f32 "
                 "{%0,%1,%2,%3},{%4,%5,%6,%7},{%8,%9},{%0,%1,%2,%3};"
                 : "+f"(c[0]), "+f"(c[1]), "+f"(c[2]), "+f"(c[3])
                 : "r"(a[0]), "r"(a[1]), "r"(a[2]), "r"(a[3]), "r"(b0), "r"(b1));
}
__device__ __forceinline__ u32 packh(float lo, float hi) {  // reg = {hi16 | lo16}
    u32 r; asm("cvt.rn.f16x2.f32 %0, %1, %2;" : "=r"(r) : "f"(hi), "f"(lo)); return r;
}
__device__ __forceinline__ void cpasync16(u32 dst, const void* src) {
    asm volatile("cp.async.cg.shared.global [%0], [%1], 16;" :: "r"(dst), "l"(src));
}
__device__ __forceinline__ void cp_commit() {
    asm volatile("cp.async.commit_group;" ::: "memory");
}
__device__ __forceinline__ void cp_wait7() {
    asm volatile("cp.async.wait_group 7;" ::: "memory");
}
__device__ __forceinline__ float sigf(float x) { return 1.f / (1.f + __expf(-x)); }
__device__ __forceinline__ float tanhg(float x) {
    float e = __expf(-2.f * fabsf(x));
    return copysignf((1.f - e) / (1.f + e), x);
}

// ---------------------------------------------------------------------------
// Fused: X[128,256] @ Wc[256,64] fp16 HMMA (m16n64 per warp). X streamed via
// per-warp 8-deep cp.async smem ring; register-resident GRU gates +
// tensor-core fc head. ONE __syncthreads in the whole kernel.
// ---------------------------------------------------------------------------
__global__ void __launch_bounds__(NTHR, 2)
fused_kernel(const float* __restrict__ x,
             const float* __restrict__ bz, const float* __restrict__ bh,
             const float* __restrict__ fc1b,
             const float* __restrict__ fc2w, const float* __restrict__ fc2b,
             float* __restrict__ out, int n)
{
    extern __shared__ char sm[];
    const u32 sb = s2u(sm);
    const int tid  = threadIdx.x;
    const int wid  = tid >> 5;
    const int lane = tid & 31;
    const int g    = lane >> 2;
    const int tg   = lane & 3;
    const int u    = lane & 3;         // 16B-unit within 64B row
    const bool ev  = (lane & 1) == 0;
    const int tile = blockIdx.x;

    // fragment k offset: tg=0 -> k0-3, tg=1 -> k8-11, tg=2 -> k4-7, tg=3 -> k12-15
    const int koff = 8 * (tg & 1) + 4 * (tg >> 1);

    // cp.async source pointers: rows g, g+8 of this warp's m16 tile, unit u
    const float* ps[2];
    #pragma unroll
    for (int q = 0; q < 2; q++) {
        int node = tile * NPB + wid * 16 + q * 8 + g;
        if (node > n - 1) node = n - 1;
        ps[q] = x + (size_t)node * NFEAT + u * 4;
    }
    const u32 xw = sb + OFF_X + (u32)wid * 1024 + (u32)g * 64 + (u32)u * 16;
    const u32 xr = sb + OFF_X + (u32)wid * 1024 + (u32)g * 64 + (u32)koff * 4;

    // ---- preamble: issue chunks 0..7 into stages 0..7 ----
    #pragma unroll
    for (int c = 0; c < NSTAGE; c++) {
        cpasync16(xw + c * XSTAGE,       ps[0] + c * 16);
        cpasync16(xw + c * XSTAGE + 512, ps[1] + c * 16);
        cp_commit();
    }

    // ---- stage W into padded smem ----
    {
        const uint4* sH = (const uint4*)g_Wh;
        #pragma unroll
        for (int it = 0; it < 8; it++) {
            int e = tid + 256 * it;
            int row = e >> 5, c16 = e & 31;
            *(uint4*)(sm + OFF_WH + row * W_STRIDE + c16 * 16) = sH[e];
        }
    }
    // ---- stage fc head + biases ----
    u32* FCq = (u32*)(sm + OFF_FC);
    float* FCf = (float*)(sm + OFF_FC);
    FCq[FCQ + tid] = g_fc1q[tid];
    FCq[FCQ + 256 + tid] = g_fc1q[256 + tid];
    if (tid < 32) {
        FCf[FW2 + tid] = fc2w[tid];
        FCf[FB1 + tid] = fc1b[tid];
        FCf[FBZ + tid] = bz[tid];
        FCf[FBH + tid] = bh[tid];
    }
    if (tid == 0) FCf[FB2] = fc2b[0];

    // ldmatrix address for B (n16 x k16, x4), validated R3-R7
    const int rowB = (lane & 7) + ((lane >> 4) & 1) * 8;
    const u32 boff = (u32)rowB * W_STRIDE + (u32)((lane >> 3) & 1) * 16;

    float acc[8][4];
    #pragma unroll
    for (int nt = 0; nt < 8; nt++)
        #pragma unroll
        for (int r = 0; r < 4; r++) acc[nt][r] = 0.f;

    __syncthreads();   // W/FC staged; the only CTA barrier

    #pragma unroll
    for (int c = 0; c < 16; c++) {
        const int st = c & (NSTAGE - 1);
        cp_wait7();            // group c complete (7 newer may be in flight)
        __syncwarp();          // other lanes' async stores visible

        // fragment loads (LDS.128, conflict-free: 8 rows x 4 units = 512B)
        float4 v0 = *(const float4*)(sm + (xr - sb) + st * XSTAGE);
        float4 v1 = *(const float4*)(sm + (xr - sb) + st * XSTAGE + 512);

        // redistribute via xor-1 shuffle, convert to fp16 A fragments
        u32 A0[4];
        {
            float s1 = ev ? v0.z : v0.x;
            float s2 = ev ? v0.w : v0.y;
            float r1 = __shfl_xor_sync(0xffffffffu, s1, 1);
            float r2 = __shfl_xor_sync(0xffffffffu, s2, 1);
            A0[0] = packh(ev ? v0.x : r1, ev ? v0.y : r2);      // row g,   kL
            A0[2] = packh(ev ? r1 : v0.z, ev ? r2 : v0.w);      // row g,   kH
            s1 = ev ? v1.z : v1.x;
            s2 = ev ? v1.w : v1.y;
            r1 = __shfl_xor_sync(0xffffffffu, s1, 1);
            r2 = __shfl_xor_sync(0xffffffffu, s2, 1);
            A0[1] = packh(ev ? v1.x : r1, ev ? v1.y : r2);      // row g+8, kL
            A0[3] = packh(ev ? r1 : v1.z, ev ? r2 : v1.w);      // row g+8, kH
        }

        // stage consumed by all lanes -> refill with chunk c+8
        __syncwarp();
        if (c + NSTAGE < 16) {
            cpasync16(xw + st * XSTAGE,       ps[0] + (c + NSTAGE) * 16);
            cpasync16(xw + st * XSTAGE + 512, ps[1] + (c + NSTAGE) * 16);
        }
        cp_commit();           // uniform group counting

        // B fragments + 8 HMMAs
        const u32 kb = (u32)c * 32;
        #pragma unroll
        for (int nq = 0; nq < 4; nq++) {
            u32 b0, b1, b2, b3;
            ldsm4(sb + OFF_WH + boff + nq * 16 * W_STRIDE + kb, b0, b1, b2, b3);
            mma16816(acc[2 * nq],     A0, b0, b1);
            mma16816(acc[2 * nq + 1], A0, b2, b3);
        }
    }

    // ================= register-resident epilogue (R6/R7, proven) =================
    u32 Afc[2][4];
    #pragma unroll
    for (int c = 0; c < 2; c++)
        #pragma unroll
        for (int half = 0; half < 2; half++) {
            int ntz = 2 * c + half;
            float2 bzv = *(float2*)(FCf + FBZ + 8 * ntz + 2 * tg);
            float2 bhv = *(float2*)(FCf + FBH + 8 * ntz + 2 * tg);
            float h0 = (1.f - sigf(acc[ntz][0] + bzv.x)) * tanhg(acc[ntz + 4][0] + bhv.x);
            float h1 = (1.f - sigf(acc[ntz][1] + bzv.y)) * tanhg(acc[ntz + 4][1] + bhv.y);
            float h2 = (1.f - sigf(acc[ntz][2] + bzv.x)) * tanhg(acc[ntz + 4][2] + bhv.x);
            float h3 = (1.f - sigf(acc[ntz][3] + bzv.y)) * tanhg(acc[ntz + 4][3] + bhv.y);
            Afc[c][half * 2 + 0] = packh(h0, h1);   // rows g
            Afc[c][half * 2 + 1] = packh(h2, h3);   // rows g+8
        }

    float a2[4][4];
    #pragma unroll
    for (int q = 0; q < 4; q++) {
        float2 b1v = *(float2*)(FCf + FB1 + 8 * q + 2 * tg);
        a2[q][0] = b1v.x; a2[q][1] = b1v.y;
        a2[q][2] = b1v.x; a2[q][3] = b1v.y;
    }
    #pragma unroll
    for (int c = 0; c < 2; c++)
        #pragma unroll
        for (int q = 0; q < 4; q++) {
            u32 bf0 = FCq[FCQ + (tg + 8 * c) * 32 + g + 8 * q];
            u32 bf1 = FCq[FCQ + (tg + 4 + 8 * c) * 32 + g + 8 * q];
            mma16816(a2[q], Afc[c], bf0, bf1);
        }

    const float b2 = FCf[FB2];
    {
        float og = 0.f, og8 = 0.f;
        #pragma unroll
        for (int q = 0; q < 4; q++) {
            float2 w2 = *(float2*)(FCf + FW2 + 8 * q + 2 * tg);
            og  = fmaf(fmaxf(a2[q][0], 0.f), w2.x, og);
            og  = fmaf(fmaxf(a2[q][1], 0.f), w2.y, og);
            og8 = fmaf(fmaxf(a2[q][2], 0.f), w2.x, og8);
            og8 = fmaf(fmaxf(a2[q][3], 0.f), w2.y, og8);
        }
        og  += __shfl_xor_sync(0xffffffffu, og, 1);
        og  += __shfl_xor_sync(0xffffffffu, og, 2);
        og8 += __shfl_xor_sync(0xffffffffu, og8, 1);
        og8 += __shfl_xor_sync(0xffffffffu, og8, 2);
        if (tg == 0) {
            int node = tile * NPB + wid * 16 + g;
            if (node < n)     out[node]     = sigf(og + b2);
            if (node + 8 < n) out[node + 8] = sigf(og8 + b2);
        }
    }
}

// ---------------------------------------------------------------------------
// Launch. Inputs: x, edge_index(dead), w_z, b_z, w_r(dead), b_r(dead),
// w_h, b_h, fc1_w, fc1_b, fc2_w, fc2_b. Output: [N,1] float.
// ---------------------------------------------------------------------------
extern "C" void kernel_launch(void* const* d_in, const int* in_sizes, int n_in,
                              void* d_out, int out_size) {
    const float* x    = (const float*)d_in[0];
    const float* wz   = (const float*)d_in[2];
    const float* bz   = (const float*)d_in[3];
    const float* wh   = (const float*)d_in[6];
    const float* bh   = (const float*)d_in[7];
    const float* fc1w = (const float*)d_in[8];
    const float* fc1b = (const float*)d_in[9];
    const float* fc2w = (const float*)d_in[10];
    const float* fc2b = (const float*)d_in[11];
    float* out = (float*)d_out;

    const int n = out_size;
    const int ntiles = (n + NPB - 1) / NPB;

    prep_kernel<<<64, 256>>>(wz, wh, fc1w);

    cudaFuncSetAttribute(fused_kernel, cudaFuncAttributeMaxDynamicSharedMemorySize, SMEM_BYTES);
    fused_kernel<<<ntiles, NTHR, SMEM_BYTES>>>(x, bz, bh, fc1b, fc2w, fc2b, out, n);
}

// round 9
// speedup vs baseline: 1.1504x; 1.1504x over previous
#include <cuda_runtime.h>
#include <cuda_fp16.h>

typedef unsigned int u32;
typedef unsigned short u16;

#define NFEAT 256
#define NPB   128          // nodes per tile (m16 per warp)
#define NTHR  256

// ---- smem layout (bytes) ----
#define W_STRIDE 528                        // 64 rows x (512B + 16B pad): ldmatrix conflict-free
#define OFF_WH   0
#define OFF_X    33792                      // X ring: 8 stages x (8 warps x 16 rows x 64B)
#define XSTAGE   8192
#define NSTAGE   8
#define OFF_FC   (OFF_X + NSTAGE * XSTAGE)  // 99328
#define FCQ   0
#define FW2   512
#define FB1   544
#define FBZ   576
#define FBH   608
#define FB2   640
#define SMEM_BYTES (OFF_FC + 642 * 4)       // 101896 -> 2 CTAs/SM

// W folded: [n=64][k=256] row-major fp16
__device__ __align__(16) u16 g_Wh[64 * 256];
// fc1 packed for B-fragments: fc1q[jp][i] = {lo: fc1[2jp][i], hi: fc1[2jp+1][i]} fp16
__device__ __align__(16) u32 g_fc1q[16 * 32];

// ---------------------------------------------------------------------------
// Prep: fold wc[j][k] = (wz[0]+wz[1]) | (wh[0]+wh[1]) (x-rows only; h0=0 kills
// the H half of the concat and the r-gate). Also pack fc1 into b-frag layout.
// ---------------------------------------------------------------------------
__global__ void prep_kernel(const float* __restrict__ wz, const float* __restrict__ wh,
                            const float* __restrict__ fc1w) {
    int idx = blockIdx.x * 256 + threadIdx.x;
    if (idx < 64 * 256) {
        int j = idx >> 8, k = idx & 255;
        const int D1 = 288 * 32;
        float wc = (j < 32) ? (wz[k * 32 + j] + wz[D1 + k * 32 + j])
                            : (wh[k * 32 + (j - 32)] + wh[D1 + k * 32 + (j - 32)]);
        __half h = __float2half_rn(wc);
        g_Wh[j * 256 + k] = *reinterpret_cast<u16*>(&h);
    }
    if (idx < 512) {
        int jp = idx >> 5, i = idx & 31;
        __half lo = __float2half_rn(fc1w[(2 * jp) * 32 + i]);
        __half hi = __float2half_rn(fc1w[(2 * jp + 1) * 32 + i]);
        g_fc1q[idx] = ((u32)*reinterpret_cast<u16*>(&hi) << 16) | *reinterpret_cast<u16*>(&lo);
    }
}

// ---------------------------------------------------------------------------
// helpers
// ---------------------------------------------------------------------------
__device__ __forceinline__ u32 s2u(const void* p) {
    u32 a;
    asm("{ .reg .u64 t; cvta.to.shared.u64 t, %1; cvt.u32.u64 %0, t; }" : "=r"(a) : "l"(p));
    return a;
}
__device__ __forceinline__ void ldsm4(u32 a, u32& r0, u32& r1, u32& r2, u32& r3) {
    asm volatile("ldmatrix.sync.aligned.m8n8.x4.shared.b16 {%0,%1,%2,%3}, [%4];"
                 : "=r"(r0), "=r"(r1), "=r"(r2), "=r"(r3) : "r"(a));
}
__device__ __forceinline__ void mma16816(float* c, const u32* a, u32 b0, u32 b1) {
    asm volatile("mma.sync.aligned.m16n8k16.row.col.f32.f16.f16.f32 "
                 "{%0,%1,%2,%3},{%4,%5,%6,%7},{%8,%9},{%0,%1,%2,%3};"
                 : "+f"(c[0]), "+f"(c[1]), "+f"(c[2]), "+f"(c[3])
                 : "r"(a[0]), "r"(a[1]), "r"(a[2]), "r"(a[3]), "r"(b0), "r"(b1));
}
__device__ __forceinline__ u32 packh(float lo, float hi) {  // reg = {hi16 | lo16}
    u32 r; asm("cvt.rn.f16x2.f32 %0, %1, %2;" : "=r"(r) : "f"(hi), "f"(lo)); return r;
}
__device__ __forceinline__ void cpasync16(u32 dst, const void* src) {
    asm volatile("cp.async.cg.shared.global [%0], [%1], 16;" :: "r"(dst), "l"(src));
}
__device__ __forceinline__ void cp_commit() {
    asm volatile("cp.async.commit_group;" ::: "memory");
}
__device__ __forceinline__ void cp_wait7() {
    asm volatile("cp.async.wait_group 7;" ::: "memory");
}
__device__ __forceinline__ float sigf(float x) { return 1.f / (1.f + __expf(-x)); }
__device__ __forceinline__ float tanhg(float x) {
    float e = __expf(-2.f * fabsf(x));
    return copysignf((1.f - e) / (1.f + e), x);
}

// ---------------------------------------------------------------------------
// Persistent fused kernel: W/FC staged ONCE; 8-deep cp.async ring streams X
// continuously across tiles; fp16 HMMA GEMM + register-resident GRU gates +
// tensor-core fc head. One __syncthreads total.
// ---------------------------------------------------------------------------
__global__ void __launch_bounds__(NTHR, 2)
fused_kernel(const float* __restrict__ x,
             const float* __restrict__ bz, const float* __restrict__ bh,
             const float* __restrict__ fc1b,
             const float* __restrict__ fc2w, const float* __restrict__ fc2b,
             float* __restrict__ out, int n, int ntiles)
{
    extern __shared__ char sm[];
    const u32 sb = s2u(sm);
    const int tid  = threadIdx.x;
    const int wid  = tid >> 5;
    const int lane = tid & 31;
    const int g    = lane >> 2;
    const int tg   = lane & 3;
    const int u    = lane & 3;         // 16B-unit within 64B row
    const bool ev  = (lane & 1) == 0;
    const int gs   = gridDim.x;

    // fragment k offset: tg=0 -> k0-3, tg=1 -> k8-11, tg=2 -> k4-7, tg=3 -> k12-15
    const int koff = 8 * (tg & 1) + 4 * (tg >> 1);

    const u32 xw = sb + OFF_X + (u32)wid * 1024 + (u32)g * 64 + (u32)u * 16;
    const u32 xr = sb + OFF_X + (u32)wid * 1024 + (u32)g * 64 + (u32)koff * 4;

    // per-tile source row pointers (rows g, g+8 of this warp's m16 slice)
    auto mk_ps = [&](int tile, const float** pp) {
        #pragma unroll
        for (int q = 0; q < 2; q++) {
            int node = tile * NPB + wid * 16 + q * 8 + g;
            if (node > n - 1) node = n - 1;
            pp[q] = x + (size_t)node * NFEAT + u * 4;
        }
    };

    int t = blockIdx.x;
    const float* psC[2];   // current tile
    const float* psN[2];   // next tile (refill target during chunks 8..15)
    if (t < ntiles) mk_ps(t, psC);

    // ---- preamble: chunks 0..7 of first tile into stages 0..7 ----
    if (t < ntiles) {
        #pragma unroll
        for (int c = 0; c < NSTAGE; c++) {
            cpasync16(xw + c * XSTAGE,       psC[0] + c * 16);
            cpasync16(xw + c * XSTAGE + 512, psC[1] + c * 16);
            cp_commit();
        }
    }

    // ---- stage W into padded smem (once) ----
    {
        const uint4* sH = (const uint4*)g_Wh;
        #pragma unroll
        for (int it = 0; it < 8; it++) {
            int e = tid + 256 * it;
            int row = e >> 5, c16 = e & 31;
            *(uint4*)(sm + OFF_WH + row * W_STRIDE + c16 * 16) = sH[e];
        }
    }
    // ---- stage fc head + biases (once) ----
    u32* FCq = (u32*)(sm + OFF_FC);
    float* FCf = (float*)(sm + OFF_FC);
    FCq[FCQ + tid] = g_fc1q[tid];
    FCq[FCQ + 256 + tid] = g_fc1q[256 + tid];
    if (tid < 32) {
        FCf[FW2 + tid] = fc2w[tid];
        FCf[FB1 + tid] = fc1b[tid];
        FCf[FBZ + tid] = bz[tid];
        FCf[FBH + tid] = bh[tid];
    }
    if (tid == 0) FCf[FB2] = fc2b[0];

    // ldmatrix address for B (n16 x k16, x4), validated R3-R8
    const int rowB = (lane & 7) + ((lane >> 4) & 1) * 8;
    const u32 boff = (u32)rowB * W_STRIDE + (u32)((lane >> 3) & 1) * 16;

    __syncthreads();   // W/FC staged; the only CTA barrier

    // =========================== persistent tile loop ===========================
    while (t < ntiles) {
        const int tn = t + gs;
        const bool hasNext = (tn < ntiles);
        if (hasNext) mk_ps(tn, psN);

        float acc[8][4];
        #pragma unroll
        for (int nt = 0; nt < 8; nt++)
            #pragma unroll
            for (int r = 0; r < 4; r++) acc[nt][r] = 0.f;

        #pragma unroll
        for (int c = 0; c < 16; c++) {
            const int st = c & (NSTAGE - 1);
            cp_wait7();            // chunk c complete (7 newer in flight)
            __syncwarp();

            float4 v0 = *(const float4*)(sm + (xr - sb) + st * XSTAGE);
            float4 v1 = *(const float4*)(sm + (xr - sb) + st * XSTAGE + 512);

            // xor-1 shuffle redistribute + fp16 pack
            u32 A0[4];
            {
                float s1 = ev ? v0.z : v0.x;
                float s2 = ev ? v0.w : v0.y;
                float r1 = __shfl_xor_sync(0xffffffffu, s1, 1);
                float r2 = __shfl_xor_sync(0xffffffffu, s2, 1);
                A0[0] = packh(ev ? v0.x : r1, ev ? v0.y : r2);
                A0[2] = packh(ev ? r1 : v0.z, ev ? r2 : v0.w);
                s1 = ev ? v1.z : v1.x;
                s2 = ev ? v1.w : v1.y;
                r1 = __shfl_xor_sync(0xffffffffu, s1, 1);
                r2 = __shfl_xor_sync(0xffffffffu, s2, 1);
                A0[1] = packh(ev ? v1.x : r1, ev ? v1.y : r2);
                A0[3] = packh(ev ? r1 : v1.z, ev ? r2 : v1.w);
            }

            // refill stage st with chunk c+8 (this tile c>=8 -> next tile c-8)
            __syncwarp();
            if (c < 8) {
                cpasync16(xw + st * XSTAGE,       psC[0] + (c + 8) * 16);
                cpasync16(xw + st * XSTAGE + 512, psC[1] + (c + 8) * 16);
            } else if (hasNext) {
                cpasync16(xw + st * XSTAGE,       psN[0] + (c - 8) * 16);
                cpasync16(xw + st * XSTAGE + 512, psN[1] + (c - 8) * 16);
            }
            cp_commit();           // uniform group counting

            // B fragments + 8 HMMAs
            const u32 kb = (u32)c * 32;
            #pragma unroll
            for (int nq = 0; nq < 4; nq++) {
                u32 b0, b1, b2, b3;
                ldsm4(sb + OFF_WH + boff + nq * 16 * W_STRIDE + kb, b0, b1, b2, b3);
                mma16816(acc[2 * nq],     A0, b0, b1);
                mma16816(acc[2 * nq + 1], A0, b2, b3);
            }
        }

        // ============== register-resident epilogue (R6-R8, proven) ==============
        u32 Afc[2][4];
        #pragma unroll
        for (int c = 0; c < 2; c++)
            #pragma unroll
            for (int half = 0; half < 2; half++) {
                int ntz = 2 * c + half;
                float2 bzv = *(float2*)(FCf + FBZ + 8 * ntz + 2 * tg);
                float2 bhv = *(float2*)(FCf + FBH + 8 * ntz + 2 * tg);
                float h0 = (1.f - sigf(acc[ntz][0] + bzv.x)) * tanhg(acc[ntz + 4][0] + bhv.x);
                float h1 = (1.f - sigf(acc[ntz][1] + bzv.y)) * tanhg(acc[ntz + 4][1] + bhv.y);
                float h2 = (1.f - sigf(acc[ntz][2] + bzv.x)) * tanhg(acc[ntz + 4][2] + bhv.x);
                float h3 = (1.f - sigf(acc[ntz][3] + bzv.y)) * tanhg(acc[ntz + 4][3] + bhv.y);
                Afc[c][half * 2 + 0] = packh(h0, h1);
                Afc[c][half * 2 + 1] = packh(h2, h3);
            }

        float a2[4][4];
        #pragma unroll
        for (int q = 0; q < 4; q++) {
            float2 b1v = *(float2*)(FCf + FB1 + 8 * q + 2 * tg);
            a2[q][0] = b1v.x; a2[q][1] = b1v.y;
            a2[q][2] = b1v.x; a2[q][3] = b1v.y;
        }
        #pragma unroll
        for (int c = 0; c < 2; c++)
            #pragma unroll
            for (int q = 0; q < 4; q++) {
                u32 bf0 = FCq[FCQ + (tg + 8 * c) * 32 + g + 8 * q];
                u32 bf1 = FCq[FCQ + (tg + 4 + 8 * c) * 32 + g + 8 * q];
                mma16816(a2[q], Afc[c], bf0, bf1);
            }

        const float b2 = FCf[FB2];
        {
            float og = 0.f, og8 = 0.f;
            #pragma unroll
            for (int q = 0; q < 4; q++) {
                float2 w2 = *(float2*)(FCf + FW2 + 8 * q + 2 * tg);
                og  = fmaf(fmaxf(a2[q][0], 0.f), w2.x, og);
                og  = fmaf(fmaxf(a2[q][1], 0.f), w2.y, og);
                og8 = fmaf(fmaxf(a2[q][2], 0.f), w2.x, og8);
                og8 = fmaf(fmaxf(a2[q][3], 0.f), w2.y, og8);
            }
            og  += __shfl_xor_sync(0xffffffffu, og, 1);
            og  += __shfl_xor_sync(0xffffffffu, og, 2);
            og8 += __shfl_xor_sync(0xffffffffu, og8, 1);
            og8 += __shfl_xor_sync(0xffffffffu, og8, 2);
            if (tg == 0) {
                int node = t * NPB + wid * 16 + g;
                if (node < n)     out[node]     = sigf(og + b2);
                if (node + 8 < n) out[node + 8] = sigf(og8 + b2);
            }
        }

        psC[0] = psN[0]; psC[1] = psN[1];
        t = tn;
    }
}

// ---------------------------------------------------------------------------
// Launch. Inputs: x, edge_index(dead), w_z, b_z, w_r(dead), b_r(dead),
// w_h, b_h, fc1_w, fc1_b, fc2_w, fc2_b. Output: [N,1] float.
// ---------------------------------------------------------------------------
extern "C" void kernel_launch(void* const* d_in, const int* in_sizes, int n_in,
                              void* d_out, int out_size) {
    const float* x    = (const float*)d_in[0];
    const float* wz   = (const float*)d_in[2];
    const float* bz   = (const float*)d_in[3];
    const float* wh   = (const float*)d_in[6];
    const float* bh   = (const float*)d_in[7];
    const float* fc1w = (const float*)d_in[8];
    const float* fc1b = (const float*)d_in[9];
    const float* fc2w = (const float*)d_in[10];
    const float* fc2b = (const float*)d_in[11];
    float* out = (float*)d_out;

    const int n = out_size;
    const int ntiles = (n + NPB - 1) / NPB;

    prep_kernel<<<64, 256>>>(wz, wh, fc1w);

    cudaFuncSetAttribute(fused_kernel, cudaFuncAttributeMaxDynamicSharedMemorySize, SMEM_BYTES);
    int grid = ntiles < 296 ? ntiles : 296;
    fused_kernel<<<grid, NTHR, SMEM_BYTES>>>(x, bz, bh, fc1b, fc2w, fc2b, out, n, ntiles);
}

// round 10
// speedup vs baseline: 1.2243x; 1.0643x over previous
#include <cuda_runtime.h>
#include <cuda_fp16.h>

typedef unsigned int u32;
typedef unsigned short u16;

#define NFEAT 256
#define NPB   128          // nodes per tile (m16 per warp)
#define NTHR  256

// ---- smem layout (bytes) ----
#define W_STRIDE 528                        // 64 rows x (512B + 16B pad): ldmatrix conflict-free
#define OFF_WH   0
#define OFF_X    33792                      // X ring: 8 stages x (8 warps x 16 rows x 64B)
#define XSTAGE   8192
#define NSTAGE   8
#define OFF_FC   (OFF_X + NSTAGE * XSTAGE)  // 99328
#define FCQ   0
#define FW2   512
#define FB1   544
#define FBZ   576
#define FBH   608
#define FB2   640
#define SMEM_BYTES (OFF_FC + 642 * 4)       // 101896 -> 2 CTAs/SM

// W folded: [n=64][k=256] row-major fp16
__device__ __align__(16) u16 g_Wh[64 * 256];
// fc1 packed for B-fragments: fc1q[jp][i] = {lo: fc1[2jp][i], hi: fc1[2jp+1][i]} fp16
__device__ __align__(16) u32 g_fc1q[16 * 32];

// ---------------------------------------------------------------------------
// Prep: fold wc[j][k] = (wz[0]+wz[1]) | (wh[0]+wh[1]) (x-rows only; h0=0 kills
// the H half of the concat and the r-gate). Also pack fc1 into b-frag layout.
// ---------------------------------------------------------------------------
__global__ void prep_kernel(const float* __restrict__ wz, const float* __restrict__ wh,
                            const float* __restrict__ fc1w) {
    int idx = blockIdx.x * 256 + threadIdx.x;
    if (idx < 64 * 256) {
        int j = idx >> 8, k = idx & 255;
        const int D1 = 288 * 32;
        float wc = (j < 32) ? (wz[k * 32 + j] + wz[D1 + k * 32 + j])
                            : (wh[k * 32 + (j - 32)] + wh[D1 + k * 32 + (j - 32)]);
        __half h = __float2half_rn(wc);
        g_Wh[j * 256 + k] = *reinterpret_cast<u16*>(&h);
    }
    if (idx < 512) {
        int jp = idx >> 5, i = idx & 31;
        __half lo = __float2half_rn(fc1w[(2 * jp) * 32 + i]);
        __half hi = __float2half_rn(fc1w[(2 * jp + 1) * 32 + i]);
        g_fc1q[idx] = ((u32)*reinterpret_cast<u16*>(&hi) << 16) | *reinterpret_cast<u16*>(&lo);
    }
}

// ---------------------------------------------------------------------------
// helpers
// ---------------------------------------------------------------------------
__device__ __forceinline__ u32 s2u(const void* p) {
    u32 a;
    asm("{ .reg .u64 t; cvta.to.shared.u64 t, %1; cvt.u32.u64 %0, t; }" : "=r"(a) : "l"(p));
    return a;
}
__device__ __forceinline__ void ldsm4(u32 a, u32& r0, u32& r1, u32& r2, u32& r3) {
    asm volatile("ldmatrix.sync.aligned.m8n8.x4.shared.b16 {%0,%1,%2,%3}, [%4];"
                 : "=r"(r0), "=r"(r1), "=r"(r2), "=r"(r3) : "r"(a));
}
__device__ __forceinline__ void mma16816(float* c, const u32* a, u32 b0, u32 b1) {
    asm volatile("mma.sync.aligned.m16n8k16.row.col.f32.f16.f16.f32 "
                 "{%0,%1,%2,%3},{%4,%5,%6,%7},{%8,%9},{%0,%1,%2,%3};"
                 : "+f"(c[0]), "+f"(c[1]), "+f"(c[2]), "+f"(c[3])
                 : "r"(a[0]), "r"(a[1]), "r"(a[2]), "r"(a[3]), "r"(b0), "r"(b1));
}
__device__ __forceinline__ u32 packh(float lo, float hi) {  // reg = {hi16 | lo16}
    u32 r; asm("cvt.rn.f16x2.f32 %0, %1, %2;" : "=r"(r) : "f"(hi), "f"(lo)); return r;
}
__device__ __forceinline__ void cpasync16(u32 dst, const void* src) {
    asm volatile("cp.async.cg.shared.global [%0], [%1], 16;" :: "r"(dst), "l"(src));
}
__device__ __forceinline__ void cp_commit() {
    asm volatile("cp.async.commit_group;" ::: "memory");
}
__device__ __forceinline__ void cp_wait7() {
    asm volatile("cp.async.wait_group 7;" ::: "memory");
}
__device__ __forceinline__ float sigf(float x) { return 1.f / (1.f + __expf(-x)); }
__device__ __forceinline__ float tanhg(float x) {
    float e = __expf(-2.f * fabsf(x));
    return copysignf((1.f - e) / (1.f + e), x);
}
__device__ __forceinline__ float2 lds64(u32 a) {
    float2 v;
    asm volatile("ld.shared.v2.f32 {%0,%1}, [%2];" : "=f"(v.x), "=f"(v.y) : "r"(a));
    return v;
}

// ---------------------------------------------------------------------------
// Persistent fused kernel. X ring stages are XOR-swizzled (16B unit ^= row&3)
// so every lane LDS.64-loads its exact mma A-fragment elements -- no shuffles.
// fp16 HMMA GEMM + register-resident GRU gates + tensor-core fc head.
// One __syncthreads total; one __syncwarp per chunk.
// ---------------------------------------------------------------------------
__global__ void __launch_bounds__(NTHR, 2)
fused_kernel(const float* __restrict__ x,
             const float* __restrict__ bz, const float* __restrict__ bh,
             const float* __restrict__ fc1b,
             const float* __restrict__ fc2w, const float* __restrict__ fc2b,
             float* __restrict__ out, int n, int ntiles)
{
    extern __shared__ char sm[];
    const u32 sb = s2u(sm);
    const int tid  = threadIdx.x;
    const int wid  = tid >> 5;
    const int lane = tid & 31;
    const int g    = lane >> 2;        // row within 8-row group
    const int tg   = lane & 3;
    const int gs   = gridDim.x;
    const int s    = g & 3;            // swizzle key

    // cp.async write: lane (g,u) writes original 16B unit u at swizzled slot u^s
    const u32 xw = sb + OFF_X + (u32)wid * 1024 + (u32)g * 64 + (u32)((tg ^ s) << 4);
    // fragment reads (LDS.64): a0 = (row g, cols 2tg..2tg+1) lives in unit tg>>1;
    // a2 = cols 2tg+8.. in unit 2|(tg>>1). Swizzled addresses:
    const u32 ra0 = sb + OFF_X + (u32)wid * 1024 + (u32)g * 64
                  + (u32)((((tg >> 1) ^ s) << 4) + ((tg & 1) << 3));
    const u32 ra2 = sb + OFF_X + (u32)wid * 1024 + (u32)g * 64
                  + (u32)(((((tg >> 1) | 2) ^ s) << 4) + ((tg & 1) << 3));

    // per-tile source row pointers (rows g, g+8 of this warp's m16 slice)
    auto mk_ps = [&](int tile, const float** pp) {
        #pragma unroll
        for (int q = 0; q < 2; q++) {
            int node = tile * NPB + wid * 16 + q * 8 + g;
            if (node > n - 1) node = n - 1;
            pp[q] = x + (size_t)node * NFEAT + tg * 4;   // 16B unit tg of the row
        }
    };

    int t = blockIdx.x;
    const float* psC[2];
    const float* psN[2];
    if (t < ntiles) mk_ps(t, psC);

    // ---- preamble: chunks 0..7 of first tile into stages 0..7 ----
    if (t < ntiles) {
        #pragma unroll
        for (int c = 0; c < NSTAGE; c++) {
            cpasync16(xw + c * XSTAGE,       psC[0] + c * 16);
            cpasync16(xw + c * XSTAGE + 512, psC[1] + c * 16);
            cp_commit();
        }
    }

    // ---- stage W into padded smem (once) ----
    {
        const uint4* sH = (const uint4*)g_Wh;
        #pragma unroll
        for (int it = 0; it < 8; it++) {
            int e = tid + 256 * it;
            int row = e >> 5, c16 = e & 31;
            *(uint4*)(sm + OFF_WH + row * W_STRIDE + c16 * 16) = sH[e];
        }
    }
    // ---- stage fc head + biases (once) ----
    u32* FCq = (u32*)(sm + OFF_FC);
    float* FCf = (float*)(sm + OFF_FC);
    FCq[FCQ + tid] = g_fc1q[tid];
    FCq[FCQ + 256 + tid] = g_fc1q[256 + tid];
    if (tid < 32) {
        FCf[FW2 + tid] = fc2w[tid];
        FCf[FB1 + tid] = fc1b[tid];
        FCf[FBZ + tid] = bz[tid];
        FCf[FBH + tid] = bh[tid];
    }
    if (tid == 0) FCf[FB2] = fc2b[0];

    // ldmatrix address for B (n16 x k16, x4), validated R3-R9
    const int rowB = (lane & 7) + ((lane >> 4) & 1) * 8;
    const u32 boff = (u32)rowB * W_STRIDE + (u32)((lane >> 3) & 1) * 16;

    __syncthreads();   // W/FC staged; the only CTA barrier

    // =========================== persistent tile loop ===========================
    while (t < ntiles) {
        const int tn = t + gs;
        const bool hasNext = (tn < ntiles);
        if (hasNext) mk_ps(tn, psN);

        float acc[8][4];
        #pragma unroll
        for (int nt = 0; nt < 8; nt++)
            #pragma unroll
            for (int r = 0; r < 4; r++) acc[nt][r] = 0.f;

        #pragma unroll
        for (int c = 0; c < 16; c++) {
            const int st = c & (NSTAGE - 1);
            cp_wait7();            // chunk c landed (7 newer in flight)
            __syncwarp();

            // direct fragment loads (swizzled LDS.64, conflict-free) + fp16 pack
            float2 d0 = lds64(ra0 + st * XSTAGE);          // row g,   k 2tg..+1
            float2 d1 = lds64(ra0 + st * XSTAGE + 512);    // row g+8
            float2 d2 = lds64(ra2 + st * XSTAGE);          // row g,   k 2tg+8..
            float2 d3 = lds64(ra2 + st * XSTAGE + 512);    // row g+8
            u32 A0[4];
            A0[0] = packh(d0.x, d0.y);
            A0[1] = packh(d1.x, d1.y);
            A0[2] = packh(d2.x, d2.y);
            A0[3] = packh(d3.x, d3.y);

            // refill stage st with chunk c+8 (in-order warp issue + LDGSTS
            // latency >> LDS latency makes this overwrite-safe without sync)
            if (c < 8) {
                cpasync16(xw + st * XSTAGE,       psC[0] + (c + 8) * 16);
                cpasync16(xw + st * XSTAGE + 512, psC[1] + (c + 8) * 16);
            } else if (hasNext) {
                cpasync16(xw + st * XSTAGE,       psN[0] + (c - 8) * 16);
                cpasync16(xw + st * XSTAGE + 512, psN[1] + (c - 8) * 16);
            }
            cp_commit();           // uniform group counting

            // B fragments + 8 HMMAs
            const u32 kb = (u32)c * 32;
            #pragma unroll
            for (int nq = 0; nq < 4; nq++) {
                u32 b0, b1, b2, b3;
                ldsm4(sb + OFF_WH + boff + nq * 16 * W_STRIDE + kb, b0, b1, b2, b3);
                mma16816(acc[2 * nq],     A0, b0, b1);
                mma16816(acc[2 * nq + 1], A0, b2, b3);
            }
        }

        // ============== register-resident epilogue (R6-R9, proven) ==============
        u32 Afc[2][4];
        #pragma unroll
        for (int c = 0; c < 2; c++)
            #pragma unroll
            for (int half = 0; half < 2; half++) {
                int ntz = 2 * c + half;
                float2 bzv = *(float2*)(FCf + FBZ + 8 * ntz + 2 * tg);
                float2 bhv = *(float2*)(FCf + FBH + 8 * ntz + 2 * tg);
                float h0 = (1.f - sigf(acc[ntz][0] + bzv.x)) * tanhg(acc[ntz + 4][0] + bhv.x);
                float h1 = (1.f - sigf(acc[ntz][1] + bzv.y)) * tanhg(acc[ntz + 4][1] + bhv.y);
                float h2 = (1.f - sigf(acc[ntz][2] + bzv.x)) * tanhg(acc[ntz + 4][2] + bhv.x);
                float h3 = (1.f - sigf(acc[ntz][3] + bzv.y)) * tanhg(acc[ntz + 4][3] + bhv.y);
                Afc[c][half * 2 + 0] = packh(h0, h1);
                Afc[c][half * 2 + 1] = packh(h2, h3);
            }

        float a2[4][4];
        #pragma unroll
        for (int q = 0; q < 4; q++) {
            float2 b1v = *(float2*)(FCf + FB1 + 8 * q + 2 * tg);
            a2[q][0] = b1v.x; a2[q][1] = b1v.y;
            a2[q][2] = b1v.x; a2[q][3] = b1v.y;
        }
        #pragma unroll
        for (int c = 0; c < 2; c++)
            #pragma unroll
            for (int q = 0; q < 4; q++) {
                u32 bf0 = FCq[FCQ + (tg + 8 * c) * 32 + g + 8 * q];
                u32 bf1 = FCq[FCQ + (tg + 4 + 8 * c) * 32 + g + 8 * q];
                mma16816(a2[q], Afc[c], bf0, bf1);
            }

        const float b2 = FCf[FB2];
        {
            float og = 0.f, og8 = 0.f;
            #pragma unroll
            for (int q = 0; q < 4; q++) {
                float2 w2 = *(float2*)(FCf + FW2 + 8 * q + 2 * tg);
                og  = fmaf(fmaxf(a2[q][0], 0.f), w2.x, og);
                og  = fmaf(fmaxf(a2[q][1], 0.f), w2.y, og);
                og8 = fmaf(fmaxf(a2[q][2], 0.f), w2.x, og8);
                og8 = fmaf(fmaxf(a2[q][3], 0.f), w2.y, og8);
            }
            og  += __shfl_xor_sync(0xffffffffu, og, 1);
            og  += __shfl_xor_sync(0xffffffffu, og, 2);
            og8 += __shfl_xor_sync(0xffffffffu, og8, 1);
            og8 += __shfl_xor_sync(0xffffffffu, og8, 2);
            if (tg == 0) {
                int node = t * NPB + wid * 16 + g;
                if (node < n)     out[node]     = sigf(og + b2);
                if (node + 8 < n) out[node + 8] = sigf(og8 + b2);
            }
        }

        psC[0] = psN[0]; psC[1] = psN[1];
        t = tn;
    }
}

// ---------------------------------------------------------------------------
// Launch. Inputs: x, edge_index(dead), w_z, b_z, w_r(dead), b_r(dead),
// w_h, b_h, fc1_w, fc1_b, fc2_w, fc2_b. Output: [N,1] float.
// ---------------------------------------------------------------------------
extern "C" void kernel_launch(void* const* d_in, const int* in_sizes, int n_in,
                              void* d_out, int out_size) {
    const float* x    = (const float*)d_in[0];
    const float* wz   = (const float*)d_in[2];
    const float* bz   = (const float*)d_in[3];
    const float* wh   = (const float*)d_in[6];
    const float* bh   = (const float*)d_in[7];
    const float* fc1w = (const float*)d_in[8];
    const float* fc1b = (const float*)d_in[9];
    const float* fc2w = (const float*)d_in[10];
    const float* fc2b = (const float*)d_in[11];
    float* out = (float*)d_out;

    const int n = out_size;
    const int ntiles = (n + NPB - 1) / NPB;

    prep_kernel<<<64, 256>>>(wz, wh, fc1w);

    cudaFuncSetAttribute(fused_kernel, cudaFuncAttributeMaxDynamicSharedMemorySize, SMEM_BYTES);
    int grid = ntiles < 296 ? ntiles : 296;
    fused_kernel<<<grid, NTHR, SMEM_BYTES>>>(x, bz, bh, fc1b, fc2w, fc2b, out, n, ntiles);
}

// round 11
// speedup vs baseline: 1.2358x; 1.0094x over previous
#include <cuda_runtime.h>
#include <cuda_fp16.h>

typedef unsigned int u32;
typedef unsigned short u16;

#define NFEAT 256
#define NPB   128          // nodes per tile (m16 per warp)
#define NTHR  256

// ---- smem layout (bytes) ----
#define W_STRIDE 528                        // 64 rows x (512B + 16B pad): ldmatrix conflict-free
#define OFF_WH   0
#define OFF_X    33792                      // X ring: 8 stages x (8 warps x 16 rows x 64B)
#define XSTAGE   8192
#define NSTAGE   8
#define OFF_FC   (OFF_X + NSTAGE * XSTAGE)  // 99328
#define FCQ   0
#define FW2   512
#define FB1   544
#define FBZ   576
#define FBH   608
#define FB2   640
#define SMEM_BYTES (OFF_FC + 642 * 4)       // 101896 -> 2 CTAs/SM

// W folded: [n=64][k=256] row-major fp16
__device__ __align__(16) u16 g_Wh[64 * 256];
// fc1 packed for B-fragments: fc1q[jp][i] = {lo: fc1[2jp][i], hi: fc1[2jp+1][i]} fp16
__device__ __align__(16) u32 g_fc1q[16 * 32];

// ---------------------------------------------------------------------------
// Prep: fold wc[j][k] = (wz[0]+wz[1]) | (wh[0]+wh[1]) (x-rows only; h0=0 kills
// the H half of the concat and the r-gate). Also pack fc1 into b-frag layout.
// ---------------------------------------------------------------------------
__global__ void prep_kernel(const float* __restrict__ wz, const float* __restrict__ wh,
                            const float* __restrict__ fc1w) {
    int idx = blockIdx.x * 256 + threadIdx.x;
    if (idx < 64 * 256) {
        int j = idx >> 8, k = idx & 255;
        const int D1 = 288 * 32;
        float wc = (j < 32) ? (wz[k * 32 + j] + wz[D1 + k * 32 + j])
                            : (wh[k * 32 + (j - 32)] + wh[D1 + k * 32 + (j - 32)]);
        __half h = __float2half_rn(wc);
        g_Wh[j * 256 + k] = *reinterpret_cast<u16*>(&h);
    }
    if (idx < 512) {
        int jp = idx >> 5, i = idx & 31;
        __half lo = __float2half_rn(fc1w[(2 * jp) * 32 + i]);
        __half hi = __float2half_rn(fc1w[(2 * jp + 1) * 32 + i]);
        g_fc1q[idx] = ((u32)*reinterpret_cast<u16*>(&hi) << 16) | *reinterpret_cast<u16*>(&lo);
    }
}

// ---------------------------------------------------------------------------
// helpers
// ---------------------------------------------------------------------------
__device__ __forceinline__ u32 s2u(const void* p) {
    u32 a;
    asm("{ .reg .u64 t; cvta.to.shared.u64 t, %1; cvt.u32.u64 %0, t; }" : "=r"(a) : "l"(p));
    return a;
}
__device__ __forceinline__ void ldsm4(u32 a, u32& r0, u32& r1, u32& r2, u32& r3) {
    asm volatile("ldmatrix.sync.aligned.m8n8.x4.shared.b16 {%0,%1,%2,%3}, [%4];"
                 : "=r"(r0), "=r"(r1), "=r"(r2), "=r"(r3) : "r"(a));
}
__device__ __forceinline__ void mma16816(float* c, const u32* a, u32 b0, u32 b1) {
    asm volatile("mma.sync.aligned.m16n8k16.row.col.f32.f16.f16.f32 "
                 "{%0,%1,%2,%3},{%4,%5,%6,%7},{%8,%9},{%0,%1,%2,%3};"
                 : "+f"(c[0]), "+f"(c[1]), "+f"(c[2]), "+f"(c[3])
                 : "r"(a[0]), "r"(a[1]), "r"(a[2]), "r"(a[3]), "r"(b0), "r"(b1));
}
__device__ __forceinline__ u32 packh(float lo, float hi) {  // reg = {hi16 | lo16}
    u32 r; asm("cvt.rn.f16x2.f32 %0, %1, %2;" : "=r"(r) : "f"(hi), "f"(lo)); return r;
}
__device__ __forceinline__ void cpasync16(u32 dst, const void* src) {
    asm volatile("cp.async.cg.shared.global [%0], [%1], 16;" :: "r"(dst), "l"(src));
}
__device__ __forceinline__ void cp_commit() {
    asm volatile("cp.async.commit_group;" ::: "memory");
}
__device__ __forceinline__ void cp_wait7() {
    asm volatile("cp.async.wait_group 7;" ::: "memory");
}
__device__ __forceinline__ float sigf(float x) { return 1.f / (1.f + __expf(-x)); }
__device__ __forceinline__ float tanhg(float x) {
    float e = __expf(-2.f * fabsf(x));
    return copysignf((1.f - e) / (1.f + e), x);
}
__device__ __forceinline__ float2 lds64(u32 a) {
    float2 v;
    asm volatile("ld.shared.v2.f32 {%0,%1}, [%2];" : "=f"(v.x), "=f"(v.y) : "r"(a));
    return v;
}

// ---------------------------------------------------------------------------
// Persistent fused kernel. XOR-swizzled 8-deep cp.async ring; A-fragment fetch
// software-pipelined ONE CHUNK AHEAD of its MMA (pipeline flows across tile
// boundaries). fp16 HMMA GEMM + register-resident GRU gates + tensor-core fc
// head. One __syncthreads total.
// ---------------------------------------------------------------------------
__global__ void __launch_bounds__(NTHR, 2)
fused_kernel(const float* __restrict__ x,
             const float* __restrict__ bz, const float* __restrict__ bh,
             const float* __restrict__ fc1b,
             const float* __restrict__ fc2w, const float* __restrict__ fc2b,
             float* __restrict__ out, int n, int ntiles)
{
    extern __shared__ char sm[];
    const u32 sb = s2u(sm);
    const int tid  = threadIdx.x;
    const int wid  = tid >> 5;
    const int lane = tid & 31;
    const int g    = lane >> 2;        // row within 8-row group
    const int tg   = lane & 3;
    const int gs   = gridDim.x;
    const int s    = g & 3;            // swizzle key

    // cp.async write: lane (g,tg) writes original 16B unit tg at swizzled slot tg^s
    const u32 xw = sb + OFF_X + (u32)wid * 1024 + (u32)g * 64 + (u32)((tg ^ s) << 4);
    // fragment reads (LDS.64) at swizzled addresses (validated R10)
    const u32 ra0 = sb + OFF_X + (u32)wid * 1024 + (u32)g * 64
                  + (u32)((((tg >> 1) ^ s) << 4) + ((tg & 1) << 3));
    const u32 ra2 = sb + OFF_X + (u32)wid * 1024 + (u32)g * 64
                  + (u32)(((((tg >> 1) | 2) ^ s) << 4) + ((tg & 1) << 3));

    // per-tile source row pointers (rows g, g+8 of this warp's m16 slice)
    auto mk_ps = [&](int tile, const float** pp) {
        #pragma unroll
        for (int q = 0; q < 2; q++) {
            int node = tile * NPB + wid * 16 + q * 8 + g;
            if (node > n - 1) node = n - 1;
            pp[q] = x + (size_t)node * NFEAT + tg * 4;
        }
    };

    int t = blockIdx.x;
    const float* psC[2];
    const float* psN[2];
    mk_ps(t, psC);

    // ---- preamble: chunks 0..7 of first tile into stages 0..7 ----
    #pragma unroll
    for (int c = 0; c < NSTAGE; c++) {
        cpasync16(xw + c * XSTAGE,       psC[0] + c * 16);
        cpasync16(xw + c * XSTAGE + 512, psC[1] + c * 16);
        cp_commit();
    }

    // ---- stage W into padded smem (once) ----
    {
        const uint4* sH = (const uint4*)g_Wh;
        #pragma unroll
        for (int it = 0; it < 8; it++) {
            int e = tid + 256 * it;
            int row = e >> 5, c16 = e & 31;
            *(uint4*)(sm + OFF_WH + row * W_STRIDE + c16 * 16) = sH[e];
        }
    }
    // ---- stage fc head + biases (once) ----
    u32* FCq = (u32*)(sm + OFF_FC);
    float* FCf = (float*)(sm + OFF_FC);
    FCq[FCQ + tid] = g_fc1q[tid];
    FCq[FCQ + 256 + tid] = g_fc1q[256 + tid];
    if (tid < 32) {
        FCf[FW2 + tid] = fc2w[tid];
        FCf[FB1 + tid] = fc1b[tid];
        FCf[FBZ + tid] = bz[tid];
        FCf[FBH + tid] = bh[tid];
    }
    if (tid == 0) FCf[FB2] = fc2b[0];

    // ldmatrix address for B (n16 x k16, x4), validated R3-R10
    const int rowB = (lane & 7) + ((lane >> 4) & 1) * 8;
    const u32 boff = (u32)rowB * W_STRIDE + (u32)((lane >> 3) & 1) * 16;

    // ---- pipeline setup: fetch chunk 0 fragments into A_cur ----
    u32 A_cur[4];
    cp_wait7();                // preamble has 8 commits -> chunk 0 landed
    __syncwarp();
    {
        float2 d0 = lds64(ra0);
        float2 d1 = lds64(ra0 + 512);
        float2 d2 = lds64(ra2);
        float2 d3 = lds64(ra2 + 512);
        A_cur[0] = packh(d0.x, d0.y);
        A_cur[1] = packh(d1.x, d1.y);
        A_cur[2] = packh(d2.x, d2.y);
        A_cur[3] = packh(d3.x, d3.y);
    }

    __syncthreads();   // W/FC staged; the only CTA barrier

    // =========================== persistent tile loop ===========================
    while (t < ntiles) {
        const int tn = t + gs;
        const bool hasNext = (tn < ntiles);
        if (hasNext) mk_ps(tn, psN);

        float acc[8][4];
        #pragma unroll
        for (int nt = 0; nt < 8; nt++)
            #pragma unroll
            for (int r = 0; r < 4; r++) acc[nt][r] = 0.f;

        #pragma unroll
        for (int c = 0; c < 16; c++) {
            const int st = c & (NSTAGE - 1);

            // refill stage st with chunk c+8 (this tile, or next tile's c-8)
            if (c < 8) {
                cpasync16(xw + st * XSTAGE,       psC[0] + (c + 8) * 16);
                cpasync16(xw + st * XSTAGE + 512, psC[1] + (c + 8) * 16);
            } else if (hasNext) {
                cpasync16(xw + st * XSTAGE,       psN[0] + (c - 8) * 16);
                cpasync16(xw + st * XSTAGE + 512, psN[1] + (c - 8) * 16);
            }
            cp_commit();       // uniform group counting

            // B fragments + 8 HMMAs on the PREFETCHED A_cur (chunk c)
            const u32 kb = (u32)c * 32;
            #pragma unroll
            for (int nq = 0; nq < 4; nq++) {
                u32 b0, b1, b2, b3;
                ldsm4(sb + OFF_WH + boff + nq * 16 * W_STRIDE + kb, b0, b1, b2, b3);
                mma16816(acc[2 * nq],     A_cur, b0, b1);
                mma16816(acc[2 * nq + 1], A_cur, b2, b3);
            }

            // fetch chunk c+1 fragments (c==15: next tile's chunk 0, already
            // staged by iters 8..15 refills) -- used NEXT iteration
            cp_wait7();        // commits = 8 + ... + (c+1) -> chunk c+1 landed
            __syncwarp();
            const int stn = (c + 1) & (NSTAGE - 1);
            float2 d0 = lds64(ra0 + stn * XSTAGE);
            float2 d1 = lds64(ra0 + stn * XSTAGE + 512);
            float2 d2 = lds64(ra2 + stn * XSTAGE);
            float2 d3 = lds64(ra2 + stn * XSTAGE + 512);
            A_cur[0] = packh(d0.x, d0.y);
            A_cur[1] = packh(d1.x, d1.y);
            A_cur[2] = packh(d2.x, d2.y);
            A_cur[3] = packh(d3.x, d3.y);
        }

        // ============== register-resident epilogue (R6-R10, proven) ==============
        u32 Afc[2][4];
        #pragma unroll
        for (int c = 0; c < 2; c++)
            #pragma unroll
            for (int half = 0; half < 2; half++) {
                int ntz = 2 * c + half;
                float2 bzv = *(float2*)(FCf + FBZ + 8 * ntz + 2 * tg);
                float2 bhv = *(float2*)(FCf + FBH + 8 * ntz + 2 * tg);
                float h0 = (1.f - sigf(acc[ntz][0] + bzv.x)) * tanhg(acc[ntz + 4][0] + bhv.x);
                float h1 = (1.f - sigf(acc[ntz][1] + bzv.y)) * tanhg(acc[ntz + 4][1] + bhv.y);
                float h2 = (1.f - sigf(acc[ntz][2] + bzv.x)) * tanhg(acc[ntz + 4][2] + bhv.x);
                float h3 = (1.f - sigf(acc[ntz][3] + bzv.y)) * tanhg(acc[ntz + 4][3] + bhv.y);
                Afc[c][half * 2 + 0] = packh(h0, h1);
                Afc[c][half * 2 + 1] = packh(h2, h3);
            }

        float a2[4][4];
        #pragma unroll
        for (int q = 0; q < 4; q++) {
            float2 b1v = *(float2*)(FCf + FB1 + 8 * q + 2 * tg);
            a2[q][0] = b1v.x; a2[q][1] = b1v.y;
            a2[q][2] = b1v.x; a2[q][3] = b1v.y;
        }
        #pragma unroll
        for (int c = 0; c < 2; c++)
            #pragma unroll
            for (int q = 0; q < 4; q++) {
                u32 bf0 = FCq[FCQ + (tg + 8 * c) * 32 + g + 8 * q];
                u32 bf1 = FCq[FCQ + (tg + 4 + 8 * c) * 32 + g + 8 * q];
                mma16816(a2[q], Afc[c], bf0, bf1);
            }

        const float b2 = FCf[FB2];
        {
            float og = 0.f, og8 = 0.f;
            #pragma unroll
            for (int q = 0; q < 4; q++) {
                float2 w2 = *(float2*)(FCf + FW2 + 8 * q + 2 * tg);
                og  = fmaf(fmaxf(a2[q][0], 0.f), w2.x, og);
                og  = fmaf(fmaxf(a2[q][1], 0.f), w2.y, og);
                og8 = fmaf(fmaxf(a2[q][2], 0.f), w2.x, og8);
                og8 = fmaf(fmaxf(a2[q][3], 0.f), w2.y, og8);
            }
            og  += __shfl_xor_sync(0xffffffffu, og, 1);
            og  += __shfl_xor_sync(0xffffffffu, og, 2);
            og8 += __shfl_xor_sync(0xffffffffu, og8, 1);
            og8 += __shfl_xor_sync(0xffffffffu, og8, 2);
            if (tg == 0) {
                int node = t * NPB + wid * 16 + g;
                if (node < n)     out[node]     = sigf(og + b2);
                if (node + 8 < n) out[node + 8] = sigf(og8 + b2);
            }
        }

        psC[0] = psN[0]; psC[1] = psN[1];
        t = tn;
    }
}

// ---------------------------------------------------------------------------
// Launch. Inputs: x, edge_index(dead), w_z, b_z, w_r(dead), b_r(dead),
// w_h, b_h, fc1_w, fc1_b, fc2_w, fc2_b. Output: [N,1] float.
// ---------------------------------------------------------------------------
extern "C" void kernel_launch(void* const* d_in, const int* in_sizes, int n_in,
                              void* d_out, int out_size) {
    const float* x    = (const float*)d_in[0];
    const float* wz   = (const float*)d_in[2];
    const float* bz   = (const float*)d_in[3];
    const float* wh   = (const float*)d_in[6];
    const float* bh   = (const float*)d_in[7];
    const float* fc1w = (const float*)d_in[8];
    const float* fc1b = (const float*)d_in[9];
    const float* fc2w = (const float*)d_in[10];
    const float* fc2b = (const float*)d_in[11];
    float* out = (float*)d_out;

    const int n = out_size;
    const int ntiles = (n + NPB - 1) / NPB;

    prep_kernel<<<64, 256>>>(wz, wh, fc1w);

    cudaFuncSetAttribute(fused_kernel, cudaFuncAttributeMaxDynamicSharedMemorySize, SMEM_BYTES);
    int grid = ntiles < 296 ? ntiles : 296;
    fused_kernel<<<grid, NTHR, SMEM_BYTES>>>(x, bz, bh, fc1b, fc2w, fc2b, out, n, ntiles);
}